// round 1
// baseline (speedup 1.0000x reference)
#include <cuda_runtime.h>
#include <math.h>

#define NN 4
#define CC 64
#define HH 256
#define WW 256
#define OC 18          // G*K*K
#define HW (HH*WW)
#define EPSF 1e-5f

// Scratch: raw conv output + BN statistics (device globals; no allocation).
__device__ float g_sigma[(size_t)NN * OC * HW];   // ~18.9 MB
__device__ float g_sum[OC], g_sumsq[OC], g_mean[OC], g_rstd[OC];

// jnp.pad mode='reflect' (mirror, edge not repeated): -1 -> 1, n -> n-2
__device__ __forceinline__ int refl(int i, int n) {
    return i < 0 ? -i : (i >= n ? 2 * n - 2 - i : i);
}

__global__ void k_zero() {
    int t = threadIdx.x;
    if (t < OC) { g_sum[t] = 0.f; g_sumsq[t] = 0.f; }
}

// ---------------------------------------------------------------------------
// Stage 1: 3x3 conv (64 -> 18 ch, reflect pad) + per-channel sum/sumsq stats.
// Block = 32x8 pixels, 1 pixel/thread, 18(+2 pad) accumulators.
// Weights in SMEM as ws[(c*9+t)*20 + o]  (stride 20 => aligned float4 loads).
// ---------------------------------------------------------------------------
__global__ void __launch_bounds__(256) k_conv(const float* __restrict__ y,
                                              const float* __restrict__ wconv) {
    __shared__ float ws[CC * 9 * 20];   // 46080 B
    __shared__ float ssum[OC], ssq[OC];

    int tx = threadIdx.x, ty = threadIdx.y;
    int tid = ty * 32 + tx;

    if (tid < OC) { ssum[tid] = 0.f; ssq[tid] = 0.f; }
    // zero the 2 pad lanes (o=18,19) of every (c,t) row
    for (int i = tid; i < CC * 9 * 2; i += 256) {
        int ct = i >> 1;
        ws[ct * 20 + 18 + (i & 1)] = 0.f;
    }
    // stage weights: ws[(c*9+t)*20 + o] = w[o][c][t]
    for (int i = tid; i < CC * 9 * OC; i += 256) {
        int o = i % OC, ct = i / OC, c = ct / 9, t = ct % 9;
        ws[ct * 20 + o] = wconv[((size_t)o * CC + c) * 9 + t];
    }
    __syncthreads();

    int w0 = blockIdx.x * 32 + tx;
    int h0 = blockIdx.y * 8 + ty;
    int n  = blockIdx.z;

    int rh[3], rw[3];
#pragma unroll
    for (int i = 0; i < 3; i++) { rh[i] = refl(h0 + i - 1, HH); rw[i] = refl(w0 + i - 1, WW); }

    float acc[20];
#pragma unroll
    for (int o = 0; o < 20; o++) acc[o] = 0.f;

    for (int c = 0; c < CC; c++) {
        const float* yc = y + ((size_t)(n * CC + c)) * HW;
        float v[9];
#pragma unroll
        for (int i = 0; i < 3; i++)
#pragma unroll
            for (int j = 0; j < 3; j++)
                v[i * 3 + j] = __ldg(&yc[rh[i] * WW + rw[j]]);

#pragma unroll
        for (int t = 0; t < 9; t++) {
            const float4* wv = (const float4*)&ws[(c * 9 + t) * 20];
            float vt = v[t];
#pragma unroll
            for (int q = 0; q < 5; q++) {
                float4 a = wv[q];
                acc[q * 4 + 0] += vt * a.x;
                acc[q * 4 + 1] += vt * a.y;
                acc[q * 4 + 2] += vt * a.z;
                acc[q * 4 + 3] += vt * a.w;
            }
        }
    }

    size_t pix = (size_t)h0 * WW + w0;
#pragma unroll
    for (int o = 0; o < OC; o++)
        g_sigma[((size_t)n * OC + o) * HW + pix] = acc[o];

    // per-channel block reduction: warp shuffle -> smem atomics -> global atomics
#pragma unroll
    for (int o = 0; o < OC; o++) {
        float s = acc[o], q = acc[o] * acc[o];
#pragma unroll
        for (int off = 16; off; off >>= 1) {
            s += __shfl_down_sync(0xffffffffu, s, off);
            q += __shfl_down_sync(0xffffffffu, q, off);
        }
        if ((tid & 31) == 0) { atomicAdd(&ssum[o], s); atomicAdd(&ssq[o], q); }
    }
    __syncthreads();
    if (tid < OC) { atomicAdd(&g_sum[tid], ssum[tid]); atomicAdd(&g_sumsq[tid], ssq[tid]); }
}

__global__ void k_stats() {
    int o = threadIdx.x;
    if (o < OC) {
        float cnt = (float)((size_t)NN * HW);
        float m = g_sum[o] / cnt;
        float v = g_sumsq[o] / cnt - m * m;
        g_mean[o] = m;
        g_rstd[o] = rsqrtf(v + EPSF);
    }
}

// ---------------------------------------------------------------------------
// Stage 3: BN-normalize + softmax(18) + write v_map + adaptive 3x3 filter.
// ---------------------------------------------------------------------------
__global__ void __launch_bounds__(256) k_apply(const float* __restrict__ y,
                                               const float* __restrict__ gamma,
                                               const float* __restrict__ beta,
                                               float* __restrict__ out) {
    int tx = threadIdx.x, ty = threadIdx.y;
    int w0 = blockIdx.x * 32 + tx;
    int h0 = blockIdx.y * 8 + ty;
    int n  = blockIdx.z;
    size_t pix = (size_t)h0 * WW + w0;

    float s[OC];
    float mx = -1e30f;
#pragma unroll
    for (int o = 0; o < OC; o++) {
        float x = g_sigma[((size_t)n * OC + o) * HW + pix];
        x = (x - g_mean[o]) * g_rstd[o] * __ldg(&gamma[o]) + __ldg(&beta[o]);
        s[o] = x;
        mx = fmaxf(mx, x);
    }
    float sum = 0.f;
#pragma unroll
    for (int o = 0; o < OC; o++) { s[o] = __expf(s[o] - mx); sum += s[o]; }
    float inv = 1.f / sum;
#pragma unroll
    for (int o = 0; o < OC; o++) s[o] *= inv;

    // v_map: (N, G, 1, 9, H*W) == channel order o = g*9+k, right after `out`
    float* vmap = out + (size_t)NN * CC * HW;
#pragma unroll
    for (int o = 0; o < OC; o++)
        vmap[((size_t)n * OC + o) * HW + pix] = s[o];

    int rh[3], rw[3];
#pragma unroll
    for (int i = 0; i < 3; i++) { rh[i] = refl(h0 + i - 1, HH); rw[i] = refl(w0 + i - 1, WW); }

#pragma unroll
    for (int g = 0; g < 2; g++) {
#pragma unroll 4
        for (int cg = 0; cg < 32; cg++) {
            int c = g * 32 + cg;
            const float* yc = y + ((size_t)(n * CC + c)) * HW;
            float a = 0.f;
#pragma unroll
            for (int i = 0; i < 3; i++)
#pragma unroll
                for (int j = 0; j < 3; j++)
                    a += __ldg(&yc[rh[i] * WW + rw[j]]) * s[g * 9 + i * 3 + j];
            out[((size_t)(n * CC + c)) * HW + pix] = a;
        }
    }
}

extern "C" void kernel_launch(void* const* d_in, const int* in_sizes, int n_in,
                              void* d_out, int out_size) {
    const float* y     = (const float*)d_in[0];
    const float* w     = (const float*)d_in[1];
    const float* gamma = (const float*)d_in[2];
    const float* beta  = (const float*)d_in[3];
    float* out = (float*)d_out;

    dim3 blk(32, 8);
    dim3 grd(WW / 32, HH / 8, NN);

    k_zero<<<1, 32>>>();
    k_conv<<<grd, blk>>>(y, w);
    k_stats<<<1, 32>>>();
    k_apply<<<grd, blk>>>(y, gamma, beta, out);
}

// round 2
// speedup vs baseline: 1.1237x; 1.1237x over previous
#include <cuda_runtime.h>
#include <math.h>

#define NN 4
#define CC 64
#define HH 256
#define WW 256
#define OC 18          // G*K*K
#define HW (HH*WW)
#define EPSF 1e-5f

// Scratch (device globals; zero-initialized at module load, kept zero by k_stats).
__device__ float g_sigma[(size_t)NN * OC * HW];   // ~18.9 MB
__device__ float g_sum[OC], g_sumsq[OC], g_mean[OC], g_rstd[OC];

// packed f32x2 FMA: d = a*b + c lanewise on two packed fp32
#define FMA_F32X2(d, a, b, c) \
    asm("fma.rn.f32x2 %0, %1, %2, %3;" : "=l"(d) : "l"(a), "l"(b), "l"(c))

__device__ __forceinline__ unsigned long long pack2(float lo, float hi) {
    unsigned long long r;
    asm("mov.b64 %0, {%1, %2};" : "=l"(r) : "r"(__float_as_uint(lo)), "r"(__float_as_uint(hi)));
    return r;
}
__device__ __forceinline__ float lo2(unsigned long long v) { return __uint_as_float((unsigned)v); }
__device__ __forceinline__ float hi2(unsigned long long v) { return __uint_as_float((unsigned)(v >> 32)); }

// jnp.pad mode='reflect' (mirror, edge not repeated)
__device__ __forceinline__ int refl(int i, int n) {
    return i < 0 ? -i : (i >= n ? 2 * n - 2 - i : i);
}

// ---------------------------------------------------------------------------
// Stage 1: 3x3 conv (64 -> 18 ch, reflect pad) + per-channel sum/sumsq stats.
// FFMA2 (f32x2) packed accumulators: 10 packed regs cover 18 outputs + 2 pad.
// ---------------------------------------------------------------------------
__global__ void __launch_bounds__(256) k_conv(const float* __restrict__ y,
                                              const float* __restrict__ wconv) {
    __shared__ __align__(16) float ws[CC * 9 * 20];   // 46080 B, rows 80B (16B-aligned)
    __shared__ float ssum[OC], ssq[OC];

    int tx = threadIdx.x, ty = threadIdx.y;
    int tid = ty * 32 + tx;

    if (tid < OC) { ssum[tid] = 0.f; ssq[tid] = 0.f; }
    for (int i = tid; i < CC * 9 * 2; i += 256) {
        int ct = i >> 1;
        ws[ct * 20 + 18 + (i & 1)] = 0.f;
    }
    for (int i = tid; i < CC * 9 * OC; i += 256) {
        int o = i % OC, ct = i / OC, c = ct / 9, t = ct % 9;
        ws[ct * 20 + o] = wconv[((size_t)o * CC + c) * 9 + t];
    }
    __syncthreads();

    int w0 = blockIdx.x * 32 + tx;
    int h0 = blockIdx.y * 8 + ty;
    int n  = blockIdx.z;

    int rh[3], rw[3];
#pragma unroll
    for (int i = 0; i < 3; i++) { rh[i] = refl(h0 + i - 1, HH); rw[i] = refl(w0 + i - 1, WW); }

    unsigned long long acc2[10];
#pragma unroll
    for (int p = 0; p < 10; p++) acc2[p] = 0ull;

    for (int c = 0; c < CC; c++) {
        const float* yc = y + ((size_t)(n * CC + c)) * HW;
        float v[9];
#pragma unroll
        for (int i = 0; i < 3; i++)
#pragma unroll
            for (int j = 0; j < 3; j++)
                v[i * 3 + j] = __ldg(&yc[rh[i] * WW + rw[j]]);

#pragma unroll
        for (int t = 0; t < 9; t++) {
            const ulonglong2* wv = (const ulonglong2*)&ws[(c * 9 + t) * 20];
            unsigned long long vt2 = pack2(v[t], v[t]);
#pragma unroll
            for (int q = 0; q < 5; q++) {
                ulonglong2 a = wv[q];
                FMA_F32X2(acc2[2 * q + 0], vt2, a.x, acc2[2 * q + 0]);
                FMA_F32X2(acc2[2 * q + 1], vt2, a.y, acc2[2 * q + 1]);
            }
        }
    }

    float acc[OC];
#pragma unroll
    for (int p = 0; p < 9; p++) { acc[2 * p] = lo2(acc2[p]); acc[2 * p + 1] = hi2(acc2[p]); }

    size_t pix = (size_t)h0 * WW + w0;
#pragma unroll
    for (int o = 0; o < OC; o++)
        g_sigma[((size_t)n * OC + o) * HW + pix] = acc[o];

#pragma unroll
    for (int o = 0; o < OC; o++) {
        float s = acc[o], q = acc[o] * acc[o];
#pragma unroll
        for (int off = 16; off; off >>= 1) {
            s += __shfl_down_sync(0xffffffffu, s, off);
            q += __shfl_down_sync(0xffffffffu, q, off);
        }
        if ((tid & 31) == 0) { atomicAdd(&ssum[o], s); atomicAdd(&ssq[o], q); }
    }
    __syncthreads();
    if (tid < OC) { atomicAdd(&g_sum[tid], ssum[tid]); atomicAdd(&g_sumsq[tid], ssq[tid]); }
}

// Stats + self-reset (replaces k_zero: next replay sees zeros again).
__global__ void k_stats() {
    int o = threadIdx.x;
    if (o < OC) {
        float cnt = (float)((size_t)NN * HW);
        float m = g_sum[o] / cnt;
        float v = g_sumsq[o] / cnt - m * m;
        g_mean[o] = m;
        g_rstd[o] = rsqrtf(v + EPSF);
        g_sum[o] = 0.f;
        g_sumsq[o] = 0.f;
    }
}

// ---------------------------------------------------------------------------
// Stage 3: BN + softmax(18) + v_map + adaptive 3x3 filter. 4 pixels/thread,
// float4 loads/stores; per channel-row: 1 LDG.128 + 2 edge scalars.
// ---------------------------------------------------------------------------
__global__ void __launch_bounds__(128) k_apply(const float* __restrict__ y,
                                               const float* __restrict__ gamma,
                                               const float* __restrict__ beta,
                                               float* __restrict__ out) {
    int tx = threadIdx.x, ty = threadIdx.y;
    int w0 = (blockIdx.x * 32 + tx) * 4;   // 4 consecutive pixels
    int h0 = blockIdx.y * 4 + ty;
    int n  = blockIdx.z;
    size_t pix = (size_t)h0 * WW + w0;

    // --- BN + softmax on 4 pixels ---
    float4 s4[OC];
    float4 mx = make_float4(-1e30f, -1e30f, -1e30f, -1e30f);
#pragma unroll
    for (int o = 0; o < OC; o++) {
        float4 x = *(const float4*)&g_sigma[((size_t)n * OC + o) * HW + pix];
        float sc = g_rstd[o] * __ldg(&gamma[o]);
        float m  = g_mean[o], b = __ldg(&beta[o]);
        x.x = (x.x - m) * sc + b; x.y = (x.y - m) * sc + b;
        x.z = (x.z - m) * sc + b; x.w = (x.w - m) * sc + b;
        s4[o] = x;
        mx.x = fmaxf(mx.x, x.x); mx.y = fmaxf(mx.y, x.y);
        mx.z = fmaxf(mx.z, x.z); mx.w = fmaxf(mx.w, x.w);
    }
    float4 sum = make_float4(0.f, 0.f, 0.f, 0.f);
#pragma unroll
    for (int o = 0; o < OC; o++) {
        s4[o].x = __expf(s4[o].x - mx.x); sum.x += s4[o].x;
        s4[o].y = __expf(s4[o].y - mx.y); sum.y += s4[o].y;
        s4[o].z = __expf(s4[o].z - mx.z); sum.z += s4[o].z;
        s4[o].w = __expf(s4[o].w - mx.w); sum.w += s4[o].w;
    }
    float4 inv = make_float4(1.f / sum.x, 1.f / sum.y, 1.f / sum.z, 1.f / sum.w);
#pragma unroll
    for (int o = 0; o < OC; o++) {
        s4[o].x *= inv.x; s4[o].y *= inv.y; s4[o].z *= inv.z; s4[o].w *= inv.w;
    }

    // v_map (N, G, 1, 9, H*W): channel order o = g*9+k, right after out
    float* vmap = out + (size_t)NN * CC * HW;
#pragma unroll
    for (int o = 0; o < OC; o++)
        *(float4*)&vmap[((size_t)n * OC + o) * HW + pix] = s4[o];

    // --- adaptive filter ---
    int rh[3];
#pragma unroll
    for (int i = 0; i < 3; i++) rh[i] = refl(h0 + i - 1, HH);
    int wl = refl(w0 - 1, WW);      // = 1 when w0==0
    int wr = refl(w0 + 4, WW);      // = 254 when w0==252

#pragma unroll
    for (int g = 0; g < 2; g++) {
#pragma unroll 2
        for (int cg = 0; cg < 32; cg++) {
            int c = g * 32 + cg;
            const float* yc = y + ((size_t)(n * CC + c)) * HW;
            float4 acc = make_float4(0.f, 0.f, 0.f, 0.f);
#pragma unroll
            for (int i = 0; i < 3; i++) {
                const float* row = yc + rh[i] * WW;
                float4 m = __ldg((const float4*)(row + w0));
                float v[6];
                v[0] = __ldg(&row[wl]); v[1] = m.x; v[2] = m.y;
                v[3] = m.z; v[4] = m.w; v[5] = __ldg(&row[wr]);
#pragma unroll
                for (int j = 0; j < 3; j++) {
                    float4 sw = s4[g * 9 + i * 3 + j];
                    acc.x += v[0 + j] * sw.x;
                    acc.y += v[1 + j] * sw.y;
                    acc.z += v[2 + j] * sw.z;
                    acc.w += v[3 + j] * sw.w;
                }
            }
            *(float4*)&out[((size_t)(n * CC + c)) * HW + pix] = acc;
        }
    }
}

extern "C" void kernel_launch(void* const* d_in, const int* in_sizes, int n_in,
                              void* d_out, int out_size) {
    const float* y     = (const float*)d_in[0];
    const float* w     = (const float*)d_in[1];
    const float* gamma = (const float*)d_in[2];
    const float* beta  = (const float*)d_in[3];
    float* out = (float*)d_out;

    dim3 cblk(32, 8), cgrd(WW / 32, HH / 8, NN);
    k_conv<<<cgrd, cblk>>>(y, w);
    k_stats<<<1, 32>>>();

    dim3 ablk(32, 4), agrd(WW / 128, HH / 4, NN);
    k_apply<<<agrd, ablk>>>(y, gamma, beta, out);
}

// round 3
// speedup vs baseline: 1.5169x; 1.3499x over previous
#include <cuda_runtime.h>
#include <math.h>

#define NN 4
#define CC 64
#define HH 256
#define WW 256
#define OC 18          // G*K*K
#define HW (HH*WW)
#define EPSF 1e-5f

// Scratch (device globals; zero-initialized at load, kept zero by k_stats).
__device__ float g_sigma[(size_t)NN * OC * HW];   // ~18.9 MB
__device__ float g_sum[OC], g_sumsq[OC], g_mean[OC], g_rstd[OC];

#define FMA_F32X2(d, a, b, c) \
    asm("fma.rn.f32x2 %0, %1, %2, %3;" : "=l"(d) : "l"(a), "l"(b), "l"(c))

__device__ __forceinline__ unsigned long long pack2(float lo, float hi) {
    unsigned long long r;
    asm("mov.b64 %0, {%1, %2};" : "=l"(r) : "r"(__float_as_uint(lo)), "r"(__float_as_uint(hi)));
    return r;
}
__device__ __forceinline__ float lo2(unsigned long long v) { return __uint_as_float((unsigned)v); }
__device__ __forceinline__ float hi2(unsigned long long v) { return __uint_as_float((unsigned)(v >> 32)); }

// jnp.pad mode='reflect' (mirror, edge not repeated)
__device__ __forceinline__ int refl(int i, int n) {
    return i < 0 ? -i : (i >= n ? 2 * n - 2 - i : i);
}

// ---------------------------------------------------------------------------
// Stage 1: 3x3 conv (64 -> 18 ch, reflect) + BN stats. 4 pixels/thread:
// weight LDS amortized 4x, neighbor loads vectorized. FFMA2 packed outputs.
// acc2[p*10+u] holds outputs (2u, 2u+1) for pixel p.
// ---------------------------------------------------------------------------
__global__ void __launch_bounds__(128) k_conv(const float* __restrict__ y,
                                              const float* __restrict__ wconv) {
    __shared__ __align__(16) float ws[CC * 9 * 20];   // 46080 B
    __shared__ float ssum[OC], ssq[OC];

    int tx = threadIdx.x, ty = threadIdx.y;
    int tid = ty * 32 + tx;

    if (tid < OC) { ssum[tid] = 0.f; ssq[tid] = 0.f; }
    for (int i = tid; i < CC * 9 * 2; i += 128) {
        int ct = i >> 1;
        ws[ct * 20 + 18 + (i & 1)] = 0.f;
    }
    for (int i = tid; i < CC * 9 * OC; i += 128) {
        int o = i % OC, ct = i / OC, c = ct / 9, t = ct % 9;
        ws[ct * 20 + o] = wconv[((size_t)o * CC + c) * 9 + t];
    }
    __syncthreads();

    int w0 = (blockIdx.x * 32 + tx) * 4;   // 4 consecutive pixels
    int h0 = blockIdx.y * 4 + ty;
    int n  = blockIdx.z;

    int rh[3];
#pragma unroll
    for (int i = 0; i < 3; i++) rh[i] = refl(h0 + i - 1, HH);
    int wl = refl(w0 - 1, WW);
    int wr = refl(w0 + 4, WW);

    unsigned long long acc2[40];
#pragma unroll
    for (int p = 0; p < 40; p++) acc2[p] = 0ull;

    for (int c = 0; c < CC; c++) {
        const float* yc = y + ((size_t)(n * CC + c)) * HW;
        float r[3][6];
#pragma unroll
        for (int i = 0; i < 3; i++) {
            const float* row = yc + rh[i] * WW;
            float4 m = __ldg((const float4*)(row + w0));
            r[i][0] = __ldg(&row[wl]);
            r[i][1] = m.x; r[i][2] = m.y; r[i][3] = m.z; r[i][4] = m.w;
            r[i][5] = __ldg(&row[wr]);
        }

#pragma unroll
        for (int i = 0; i < 3; i++) {
#pragma unroll
            for (int j = 0; j < 3; j++) {
                const ulonglong2* wv = (const ulonglong2*)&ws[(c * 9 + i * 3 + j) * 20];
                ulonglong2 wq0 = wv[0], wq1 = wv[1], wq2 = wv[2], wq3 = wv[3], wq4 = wv[4];
                unsigned long long wqa[10] = {wq0.x, wq0.y, wq1.x, wq1.y, wq2.x,
                                              wq2.y, wq3.x, wq3.y, wq4.x, wq4.y};
#pragma unroll
                for (int p = 0; p < 4; p++) {
                    unsigned long long vt2 = pack2(r[i][j + p], r[i][j + p]);
#pragma unroll
                    for (int q = 0; q < 10; q++)
                        FMA_F32X2(acc2[p * 10 + q], vt2, wqa[q], acc2[p * 10 + q]);
                }
            }
        }
    }

    size_t pix = (size_t)h0 * WW + w0;
#pragma unroll
    for (int o = 0; o < OC; o++) {
        int u = o >> 1;
        float4 vv;
        if (o & 1) {
            vv = make_float4(hi2(acc2[u]), hi2(acc2[10 + u]),
                             hi2(acc2[20 + u]), hi2(acc2[30 + u]));
        } else {
            vv = make_float4(lo2(acc2[u]), lo2(acc2[10 + u]),
                             lo2(acc2[20 + u]), lo2(acc2[30 + u]));
        }
        *(float4*)&g_sigma[((size_t)n * OC + o) * HW + pix] = vv;

        float s = vv.x + vv.y + vv.z + vv.w;
        float q = vv.x * vv.x + vv.y * vv.y + vv.z * vv.z + vv.w * vv.w;
#pragma unroll
        for (int off = 16; off; off >>= 1) {
            s += __shfl_down_sync(0xffffffffu, s, off);
            q += __shfl_down_sync(0xffffffffu, q, off);
        }
        if ((tid & 31) == 0) { atomicAdd(&ssum[o], s); atomicAdd(&ssq[o], q); }
    }
    __syncthreads();
    if (tid < OC) { atomicAdd(&g_sum[tid], ssum[tid]); atomicAdd(&g_sumsq[tid], ssq[tid]); }
}

// Stats + self-reset (next graph replay sees zeros again).
__global__ void k_stats() {
    int o = threadIdx.x;
    if (o < OC) {
        float cnt = (float)((size_t)NN * HW);
        float m = g_sum[o] / cnt;
        float v = g_sumsq[o] / cnt - m * m;
        g_mean[o] = m;
        g_rstd[o] = rsqrtf(v + EPSF);
        g_sum[o] = 0.f;
        g_sumsq[o] = 0.f;
    }
}

// ---------------------------------------------------------------------------
// Stage 3: BN + softmax(18) + v_map + adaptive 3x3 filter. 4 pixels/thread.
// ---------------------------------------------------------------------------
__global__ void __launch_bounds__(128) k_apply(const float* __restrict__ y,
                                               const float* __restrict__ gamma,
                                               const float* __restrict__ beta,
                                               float* __restrict__ out) {
    int tx = threadIdx.x, ty = threadIdx.y;
    int w0 = (blockIdx.x * 32 + tx) * 4;
    int h0 = blockIdx.y * 4 + ty;
    int n  = blockIdx.z;
    size_t pix = (size_t)h0 * WW + w0;

    float4 s4[OC];
    float4 mx = make_float4(-1e30f, -1e30f, -1e30f, -1e30f);
#pragma unroll
    for (int o = 0; o < OC; o++) {
        float4 x = *(const float4*)&g_sigma[((size_t)n * OC + o) * HW + pix];
        float sc = g_rstd[o] * __ldg(&gamma[o]);
        float m  = g_mean[o], b = __ldg(&beta[o]);
        x.x = (x.x - m) * sc + b; x.y = (x.y - m) * sc + b;
        x.z = (x.z - m) * sc + b; x.w = (x.w - m) * sc + b;
        s4[o] = x;
        mx.x = fmaxf(mx.x, x.x); mx.y = fmaxf(mx.y, x.y);
        mx.z = fmaxf(mx.z, x.z); mx.w = fmaxf(mx.w, x.w);
    }
    float4 sum = make_float4(0.f, 0.f, 0.f, 0.f);
#pragma unroll
    for (int o = 0; o < OC; o++) {
        s4[o].x = __expf(s4[o].x - mx.x); sum.x += s4[o].x;
        s4[o].y = __expf(s4[o].y - mx.y); sum.y += s4[o].y;
        s4[o].z = __expf(s4[o].z - mx.z); sum.z += s4[o].z;
        s4[o].w = __expf(s4[o].w - mx.w); sum.w += s4[o].w;
    }
    float4 inv = make_float4(1.f / sum.x, 1.f / sum.y, 1.f / sum.z, 1.f / sum.w);
#pragma unroll
    for (int o = 0; o < OC; o++) {
        s4[o].x *= inv.x; s4[o].y *= inv.y; s4[o].z *= inv.z; s4[o].w *= inv.w;
    }

    float* vmap = out + (size_t)NN * CC * HW;
#pragma unroll
    for (int o = 0; o < OC; o++)
        *(float4*)&vmap[((size_t)n * OC + o) * HW + pix] = s4[o];

    int rh[3];
#pragma unroll
    for (int i = 0; i < 3; i++) rh[i] = refl(h0 + i - 1, HH);
    int wl = refl(w0 - 1, WW);
    int wr = refl(w0 + 4, WW);

#pragma unroll
    for (int g = 0; g < 2; g++) {
#pragma unroll 2
        for (int cg = 0; cg < 32; cg++) {
            int c = g * 32 + cg;
            const float* yc = y + ((size_t)(n * CC + c)) * HW;
            float4 acc = make_float4(0.f, 0.f, 0.f, 0.f);
#pragma unroll
            for (int i = 0; i < 3; i++) {
                const float* row = yc + rh[i] * WW;
                float4 m = __ldg((const float4*)(row + w0));
                float v[6];
                v[0] = __ldg(&row[wl]); v[1] = m.x; v[2] = m.y;
                v[3] = m.z; v[4] = m.w; v[5] = __ldg(&row[wr]);
#pragma unroll
                for (int j = 0; j < 3; j++) {
                    float4 sw = s4[g * 9 + i * 3 + j];
                    acc.x += v[0 + j] * sw.x;
                    acc.y += v[1 + j] * sw.y;
                    acc.z += v[2 + j] * sw.z;
                    acc.w += v[3 + j] * sw.w;
                }
            }
            *(float4*)&out[((size_t)(n * CC + c)) * HW + pix] = acc;
        }
    }
}

extern "C" void kernel_launch(void* const* d_in, const int* in_sizes, int n_in,
                              void* d_out, int out_size) {
    const float* y     = (const float*)d_in[0];
    const float* w     = (const float*)d_in[1];
    const float* gamma = (const float*)d_in[2];
    const float* beta  = (const float*)d_in[3];
    float* out = (float*)d_out;

    dim3 cblk(32, 4), cgrd(WW / 128, HH / 4, NN);
    k_conv<<<cgrd, cblk>>>(y, w);
    k_stats<<<1, 32>>>();

    dim3 ablk(32, 4), agrd(WW / 128, HH / 4, NN);
    k_apply<<<agrd, ablk>>>(y, gamma, beta, out);
}

// round 4
// speedup vs baseline: 1.5565x; 1.0261x over previous
#include <cuda_runtime.h>
#include <math.h>

#define NN 4
#define CC 64
#define HH 256
#define WW 256
#define OC 18          // G*K*K
#define HW (HH*WW)
#define EPSF 1e-5f

// Scratch (device globals; zero-initialized at load, kept zero by k_stats).
__device__ float g_sigma[(size_t)NN * OC * HW];   // ~18.9 MB
__device__ float g_sum[OC], g_sumsq[OC], g_mean[OC], g_rstd[OC];

#define FMA_F32X2(d, a, b, c) \
    asm("fma.rn.f32x2 %0, %1, %2, %3;" : "=l"(d) : "l"(a), "l"(b), "l"(c))

__device__ __forceinline__ unsigned long long pack2(float v) {
    unsigned long long r;
    asm("mov.b64 %0, {%1, %1};" : "=l"(r) : "r"(__float_as_uint(v)));
    return r;
}
__device__ __forceinline__ float lo2(unsigned long long v) { return __uint_as_float((unsigned)v); }
__device__ __forceinline__ float hi2(unsigned long long v) { return __uint_as_float((unsigned)(v >> 32)); }

// jnp.pad mode='reflect' (mirror, edge not repeated)
__device__ __forceinline__ int refl(int i, int n) {
    return i < 0 ? -i : (i >= n ? 2 * n - 2 - i : i);
}

// ---------------------------------------------------------------------------
// Stage 1: 3x3 conv (64 -> 18 ch, reflect) + BN stats.
// 4 pixels/thread, 9 packed FFMA2 accumulators per pixel (no pad lanes),
// software-pipelined channel loop (prefetch next channel's mid float4s).
// acc2[p*9+q] = outputs (2q, 2q+1) for pixel p.
// ---------------------------------------------------------------------------

// One tap: 9 packed weights vs 4 pixels' broadcast values va..vd.
#define TAP(wp, va, vb, vc, vd)                                                \
    {                                                                          \
        ulonglong2 w01 = *(const ulonglong2*)((wp));                           \
        ulonglong2 w23 = *(const ulonglong2*)((wp) + 4);                       \
        ulonglong2 w45 = *(const ulonglong2*)((wp) + 8);                       \
        ulonglong2 w67 = *(const ulonglong2*)((wp) + 12);                      \
        unsigned long long w8 = *(const unsigned long long*)((wp) + 16);       \
        FMA_F32X2(acc2[0], va, w01.x, acc2[0]);                                \
        FMA_F32X2(acc2[1], va, w01.y, acc2[1]);                                \
        FMA_F32X2(acc2[2], va, w23.x, acc2[2]);                                \
        FMA_F32X2(acc2[3], va, w23.y, acc2[3]);                                \
        FMA_F32X2(acc2[4], va, w45.x, acc2[4]);                                \
        FMA_F32X2(acc2[5], va, w45.y, acc2[5]);                                \
        FMA_F32X2(acc2[6], va, w67.x, acc2[6]);                                \
        FMA_F32X2(acc2[7], va, w67.y, acc2[7]);                                \
        FMA_F32X2(acc2[8], va, w8,    acc2[8]);                                \
        FMA_F32X2(acc2[9],  vb, w01.x, acc2[9]);                               \
        FMA_F32X2(acc2[10], vb, w01.y, acc2[10]);                              \
        FMA_F32X2(acc2[11], vb, w23.x, acc2[11]);                              \
        FMA_F32X2(acc2[12], vb, w23.y, acc2[12]);                              \
        FMA_F32X2(acc2[13], vb, w45.x, acc2[13]);                              \
        FMA_F32X2(acc2[14], vb, w45.y, acc2[14]);                              \
        FMA_F32X2(acc2[15], vb, w67.x, acc2[15]);                              \
        FMA_F32X2(acc2[16], vb, w67.y, acc2[16]);                              \
        FMA_F32X2(acc2[17], vb, w8,    acc2[17]);                              \
        FMA_F32X2(acc2[18], vc, w01.x, acc2[18]);                              \
        FMA_F32X2(acc2[19], vc, w01.y, acc2[19]);                              \
        FMA_F32X2(acc2[20], vc, w23.x, acc2[20]);                              \
        FMA_F32X2(acc2[21], vc, w23.y, acc2[21]);                              \
        FMA_F32X2(acc2[22], vc, w45.x, acc2[22]);                              \
        FMA_F32X2(acc2[23], vc, w45.y, acc2[23]);                              \
        FMA_F32X2(acc2[24], vc, w67.x, acc2[24]);                              \
        FMA_F32X2(acc2[25], vc, w67.y, acc2[25]);                              \
        FMA_F32X2(acc2[26], vc, w8,    acc2[26]);                              \
        FMA_F32X2(acc2[27], vd, w01.x, acc2[27]);                              \
        FMA_F32X2(acc2[28], vd, w01.y, acc2[28]);                              \
        FMA_F32X2(acc2[29], vd, w23.x, acc2[29]);                              \
        FMA_F32X2(acc2[30], vd, w23.y, acc2[30]);                              \
        FMA_F32X2(acc2[31], vd, w45.x, acc2[31]);                              \
        FMA_F32X2(acc2[32], vd, w45.y, acc2[32]);                              \
        FMA_F32X2(acc2[33], vd, w67.x, acc2[33]);                              \
        FMA_F32X2(acc2[34], vd, w67.y, acc2[34]);                              \
        FMA_F32X2(acc2[35], vd, w8,    acc2[35]);                              \
    }

// One image row: taps ordered j=1 (mids only), j=0, j=2 so edge packs are
// deferred ~36 FFMA2 past their L1-hit loads.
#define ROW(m, el, er, wrow3)                                                  \
    {                                                                          \
        unsigned long long v1 = pack2((m).x), v2 = pack2((m).y);               \
        unsigned long long v3 = pack2((m).z), v4 = pack2((m).w);               \
        TAP((wrow3) + 20, v1, v2, v3, v4)                                      \
        unsigned long long v0 = pack2(el);                                     \
        TAP((wrow3), v0, v1, v2, v3)                                           \
        unsigned long long v5 = pack2(er);                                     \
        TAP((wrow3) + 40, v2, v3, v4, v5)                                      \
    }

__global__ void __launch_bounds__(128, 4) k_conv(const float* __restrict__ y,
                                                 const float* __restrict__ wconv) {
    __shared__ __align__(16) float ws[CC * 9 * 20];   // 46080 B (stride 20, 18 used)
    __shared__ float ssum[OC], ssq[OC];

    int tx = threadIdx.x, ty = threadIdx.y;
    int tid = ty * 32 + tx;

    if (tid < OC) { ssum[tid] = 0.f; ssq[tid] = 0.f; }
    for (int i = tid; i < CC * 9 * OC; i += 128) {
        int o = i % OC, ct = i / OC;
        ws[ct * 20 + o] = wconv[((size_t)o * CC + ct / 9) * 9 + (ct % 9)];
    }
    __syncthreads();

    int w0 = (blockIdx.x * 32 + tx) * 4;
    int h0 = blockIdx.y * 4 + ty;
    int n  = blockIdx.z;

    int rh[3];
#pragma unroll
    for (int i = 0; i < 3; i++) rh[i] = refl(h0 + i - 1, HH);
    int wl = refl(w0 - 1, WW);
    int wr = refl(w0 + 4, WW);

    // per-row offsets (elements)
    int om0 = rh[0] * WW + w0, om1 = rh[1] * WW + w0, om2 = rh[2] * WW + w0;
    int ol0 = rh[0] * WW + wl, ol1 = rh[1] * WW + wl, ol2 = rh[2] * WW + wl;
    int or0 = rh[0] * WW + wr, or1 = rh[1] * WW + wr, or2 = rh[2] * WW + wr;

    unsigned long long acc2[36];
#pragma unroll
    for (int p = 0; p < 36; p++) acc2[p] = 0ull;

    const float* yc = y + ((size_t)n * CC) * HW;

    // prime mids for channel 0
    float4 cm0 = __ldg((const float4*)(yc + om0));
    float4 cm1 = __ldg((const float4*)(yc + om1));
    float4 cm2 = __ldg((const float4*)(yc + om2));

#pragma unroll 2
    for (int c = 0; c < CC; c++) {
        // prefetch next channel's mids (clamped pointer on last iter: valid, discarded)
        const float* ycn = yc + ((c < CC - 1) ? HW : 0);
        float4 nm0 = __ldg((const float4*)(ycn + om0));
        float4 nm1 = __ldg((const float4*)(ycn + om1));
        float4 nm2 = __ldg((const float4*)(ycn + om2));

        // current-channel edges (L1 hits: same lines as neighbors' mids)
        float el0 = __ldg(yc + ol0), er0 = __ldg(yc + or0);
        float el1 = __ldg(yc + ol1), er1 = __ldg(yc + or1);
        float el2 = __ldg(yc + ol2), er2 = __ldg(yc + or2);

        const float* wrow = &ws[c * 180];
        ROW(cm0, el0, er0, wrow)
        ROW(cm1, el1, er1, wrow + 60)
        ROW(cm2, el2, er2, wrow + 120)

        yc = ycn;
        cm0 = nm0; cm1 = nm1; cm2 = nm2;
    }

    size_t pix = (size_t)h0 * WW + w0;
#pragma unroll
    for (int o = 0; o < OC; o++) {
        int u = o >> 1;
        float4 vv;
        if (o & 1) {
            vv = make_float4(hi2(acc2[u]), hi2(acc2[9 + u]),
                             hi2(acc2[18 + u]), hi2(acc2[27 + u]));
        } else {
            vv = make_float4(lo2(acc2[u]), lo2(acc2[9 + u]),
                             lo2(acc2[18 + u]), lo2(acc2[27 + u]));
        }
        *(float4*)&g_sigma[((size_t)n * OC + o) * HW + pix] = vv;

        float s = vv.x + vv.y + vv.z + vv.w;
        float q = vv.x * vv.x + vv.y * vv.y + vv.z * vv.z + vv.w * vv.w;
#pragma unroll
        for (int off = 16; off; off >>= 1) {
            s += __shfl_down_sync(0xffffffffu, s, off);
            q += __shfl_down_sync(0xffffffffu, q, off);
        }
        if ((tid & 31) == 0) { atomicAdd(&ssum[o], s); atomicAdd(&ssq[o], q); }
    }
    __syncthreads();
    if (tid < OC) { atomicAdd(&g_sum[tid], ssum[tid]); atomicAdd(&g_sumsq[tid], ssq[tid]); }
}

// Stats + self-reset (next graph replay sees zeros again).
__global__ void k_stats() {
    int o = threadIdx.x;
    if (o < OC) {
        float cnt = (float)((size_t)NN * HW);
        float m = g_sum[o] / cnt;
        float v = g_sumsq[o] / cnt - m * m;
        g_mean[o] = m;
        g_rstd[o] = rsqrtf(v + EPSF);
        g_sum[o] = 0.f;
        g_sumsq[o] = 0.f;
    }
}

// ---------------------------------------------------------------------------
// Stage 3: BN + softmax(18) + v_map + adaptive 3x3 filter. 4 pixels/thread.
// ---------------------------------------------------------------------------
__global__ void __launch_bounds__(128) k_apply(const float* __restrict__ y,
                                               const float* __restrict__ gamma,
                                               const float* __restrict__ beta,
                                               float* __restrict__ out) {
    int tx = threadIdx.x, ty = threadIdx.y;
    int w0 = (blockIdx.x * 32 + tx) * 4;
    int h0 = blockIdx.y * 4 + ty;
    int n  = blockIdx.z;
    size_t pix = (size_t)h0 * WW + w0;

    float4 s4[OC];
    float4 mx = make_float4(-1e30f, -1e30f, -1e30f, -1e30f);
#pragma unroll
    for (int o = 0; o < OC; o++) {
        float4 x = *(const float4*)&g_sigma[((size_t)n * OC + o) * HW + pix];
        float sc = g_rstd[o] * __ldg(&gamma[o]);
        float m  = g_mean[o], b = __ldg(&beta[o]);
        x.x = (x.x - m) * sc + b; x.y = (x.y - m) * sc + b;
        x.z = (x.z - m) * sc + b; x.w = (x.w - m) * sc + b;
        s4[o] = x;
        mx.x = fmaxf(mx.x, x.x); mx.y = fmaxf(mx.y, x.y);
        mx.z = fmaxf(mx.z, x.z); mx.w = fmaxf(mx.w, x.w);
    }
    float4 sum = make_float4(0.f, 0.f, 0.f, 0.f);
#pragma unroll
    for (int o = 0; o < OC; o++) {
        s4[o].x = __expf(s4[o].x - mx.x); sum.x += s4[o].x;
        s4[o].y = __expf(s4[o].y - mx.y); sum.y += s4[o].y;
        s4[o].z = __expf(s4[o].z - mx.z); sum.z += s4[o].z;
        s4[o].w = __expf(s4[o].w - mx.w); sum.w += s4[o].w;
    }
    float4 inv = make_float4(1.f / sum.x, 1.f / sum.y, 1.f / sum.z, 1.f / sum.w);
#pragma unroll
    for (int o = 0; o < OC; o++) {
        s4[o].x *= inv.x; s4[o].y *= inv.y; s4[o].z *= inv.z; s4[o].w *= inv.w;
    }

    float* vmap = out + (size_t)NN * CC * HW;
#pragma unroll
    for (int o = 0; o < OC; o++)
        *(float4*)&vmap[((size_t)n * OC + o) * HW + pix] = s4[o];

    int rh[3];
#pragma unroll
    for (int i = 0; i < 3; i++) rh[i] = refl(h0 + i - 1, HH);
    int wl = refl(w0 - 1, WW);
    int wr = refl(w0 + 4, WW);

#pragma unroll
    for (int g = 0; g < 2; g++) {
#pragma unroll 2
        for (int cg = 0; cg < 32; cg++) {
            int c = g * 32 + cg;
            const float* yc = y + ((size_t)(n * CC + c)) * HW;
            float4 acc = make_float4(0.f, 0.f, 0.f, 0.f);
#pragma unroll
            for (int i = 0; i < 3; i++) {
                const float* row = yc + rh[i] * WW;
                float4 m = __ldg((const float4*)(row + w0));
                float v[6];
                v[0] = __ldg(&row[wl]); v[1] = m.x; v[2] = m.y;
                v[3] = m.z; v[4] = m.w; v[5] = __ldg(&row[wr]);
#pragma unroll
                for (int j = 0; j < 3; j++) {
                    float4 sw = s4[g * 9 + i * 3 + j];
                    acc.x += v[0 + j] * sw.x;
                    acc.y += v[1 + j] * sw.y;
                    acc.z += v[2 + j] * sw.z;
                    acc.w += v[3 + j] * sw.w;
                }
            }
            *(float4*)&out[((size_t)(n * CC + c)) * HW + pix] = acc;
        }
    }
}

extern "C" void kernel_launch(void* const* d_in, const int* in_sizes, int n_in,
                              void* d_out, int out_size) {
    const float* y     = (const float*)d_in[0];
    const float* w     = (const float*)d_in[1];
    const float* gamma = (const float*)d_in[2];
    const float* beta  = (const float*)d_in[3];
    float* out = (float*)d_out;

    dim3 cblk(32, 4), cgrd(WW / 128, HH / 4, NN);
    k_conv<<<cgrd, cblk>>>(y, w);
    k_stats<<<1, 32>>>();

    dim3 ablk(32, 4), agrd(WW / 128, HH / 4, NN);
    k_apply<<<agrd, ablk>>>(y, gamma, beta, out);
}